// round 14
// baseline (speedup 1.0000x reference)
#include <cuda_runtime.h>

#define N_NODES 50000
#define N_EDGES 800000
#define DIM 64
#define NCHUNK 49            // ceil(50000/1024)
#define PAD 65               // smem row pitch (floats), conflict-free

// Scratch (device globals — no allocation allowed). BSS zero-init at load.
// g_deg is re-zeroed inside k_scan_chain each run; chain flags use epoch
// counters (monotonic) so no reset is needed across graph replays.
__device__ int   g_deg[N_NODES];
__device__ int   g_row[N_NODES + 1];
__device__ int   g_cur[N_NODES];
__device__ int   g_col[N_EDGES];
__device__ float g_x1[N_NODES * DIM];
__device__ int   g_chain_val[NCHUNK];
__device__ int   g_chain_flag[NCHUNK];   // epoch counts, never reset

// ------------------------------------------------------------------ hist
__global__ void k_hist(const int* __restrict__ ei) {
    int t = blockIdx.x * blockDim.x + threadIdx.x;
    if (t < N_EDGES / 4) {
        int4 d = ((const int4*)(ei + N_EDGES))[t];
        atomicAdd(&g_deg[d.x], 1);
        atomicAdd(&g_deg[d.y], 1);
        atomicAdd(&g_deg[d.z], 1);
        atomicAdd(&g_deg[d.w], 1);
    }
}

// -------------------- chained exclusive scan (one kernel, 49 blocks) -----
__global__ void __launch_bounds__(1024) k_scan_chain() {
    __shared__ int wsum[32];
    __shared__ int s_base;
    int t = threadIdx.x, lane = t & 31, wid = t >> 5;
    int b = blockIdx.x;
    int i = b * 1024 + t;
    int v = 0;
    if (i < N_NODES) { v = g_deg[i]; g_deg[i] = 0; }
    int sc = v;
    #pragma unroll
    for (int off = 1; off < 32; off <<= 1) {
        int n = __shfl_up_sync(0xffffffffu, sc, off);
        if (lane >= off) sc += n;
    }
    if (lane == 31) wsum[wid] = sc;
    __syncthreads();
    if (wid == 0) {
        int w = wsum[lane];
        #pragma unroll
        for (int off = 1; off < 32; off <<= 1) {
            int n = __shfl_up_sync(0xffffffffu, w, off);
            if (lane >= off) w += n;
        }
        wsum[lane] = w;
    }
    __syncthreads();
    int wpre  = (wid > 0) ? wsum[wid - 1] : 0;
    int total = wsum[31];
    if (t == 0) {
        int E = g_chain_flag[b];
        int base = 0;
        if (b > 0) {
            while (atomicAdd(&g_chain_flag[b - 1], 0) <= E) {}
            __threadfence();
            base = g_chain_val[b - 1];
        }
        g_chain_val[b] = base + total;
        __threadfence();
        atomicExch(&g_chain_flag[b], E + 1);
        s_base = base;
    }
    __syncthreads();
    int ex = s_base + wpre + sc - v;
    if (i < N_NODES) { g_row[i] = ex; g_cur[i] = ex; }
    if (i == 0) g_row[N_NODES] = N_EDGES;
}

// --------------------------------------------------------------- scatter
__global__ void k_scatter(const int* __restrict__ ei) {
    int t = blockIdx.x * blockDim.x + threadIdx.x;
    if (t < N_EDGES / 4) {
        int4 s = ((const int4*)ei)[t];
        int4 d = ((const int4*)(ei + N_EDGES))[t];
        g_col[atomicAdd(&g_cur[d.x], 1)] = s.x;
        g_col[atomicAdd(&g_cur[d.y], 1)] = s.y;
        g_col[atomicAdd(&g_cur[d.z], 1)] = s.z;
        g_col[atomicAdd(&g_cur[d.w], 1)] = s.w;
    }
}

// ------------- fused layer: aggregation + GEMM + bias + relu --------------
// Block owns 128 nodes, 512 threads = 16 warps.
// Gather phase interleaves TWO nodes per warp-iteration (8 loads in flight)
// to double MLP in the latency-bound phase. Per-node sum order unchanged.
__global__ void __launch_bounds__(512, 2) k_layer(const float* __restrict__ x,
                                                  const float* __restrict__ Wl,
                                                  const float* __restrict__ bl,
                                                  const float* __restrict__ Wr,
                                                  float* __restrict__ out) {
    extern __shared__ float sm[];
    float* wl_s = sm;                     // [64*64]
    float* wr_s = sm + 4096;              // [64*64]
    float* a_s  = sm + 8192;              // [128][PAD]
    float* x_s  = sm + 8192 + 128 * PAD;  // [128][PAD]

    const int tid   = threadIdx.x;
    const int lane  = tid & 31;
    const int w     = tid >> 5;           // warp 0..15
    const int node0 = blockIdx.x * 128;

    for (int i = tid; i < DIM * DIM / 4; i += 512) {
        ((float4*)wl_s)[i] = ((const float4*)Wl)[i];
        ((float4*)wr_s)[i] = ((const float4*)Wr)[i];
    }
    {
        int nl = tid & 127;
        int kh = (tid >> 7) * 16;
        int node = node0 + nl;
        if (node < N_NODES) {
            const float4* xr = (const float4*)(x + node * DIM + kh);
            #pragma unroll
            for (int j = 0; j < 4; j++) {
                float4 v = xr[j];
                int k = kh + j * 4;
                x_s[nl * PAD + k + 0] = v.x;
                x_s[nl * PAD + k + 1] = v.y;
                x_s[nl * PAD + k + 2] = v.z;
                x_s[nl * PAD + k + 3] = v.w;
            }
        }
    }
    __syncthreads();

    // aggregation: warp w -> node pairs (w*8+2q, w*8+2q+1), q=0..3
    const float2* xs = (const float2*)x;
    #pragma unroll 1
    for (int q = 0; q < 4; q++) {
        int nl0 = w * 8 + 2 * q;
        int n0  = node0 + nl0;
        if (n0 >= N_NODES) break;
        int n1  = n0 + 1;
        bool v1 = (n1 < N_NODES) ;

        float a0 = x_s[nl0 * PAD + 2 * lane];
        float a1 = x_s[nl0 * PAD + 2 * lane + 1];
        float b0 = 0.f, b1 = 0.f;
        if (v1) {
            b0 = x_s[(nl0 + 1) * PAD + 2 * lane];
            b1 = x_s[(nl0 + 1) * PAD + 2 * lane + 1];
        }

        int s0 = g_row[n0];
        int c0 = g_row[n0 + 1] - s0;
        int s1 = 0, c1 = 0;
        if (v1) { s1 = g_row[n1]; c1 = g_row[n1 + 1] - s1; }

        int cmax = c0 > c1 ? c0 : c1;
        for (int base = 0; base < cmax; base += 32) {
            int m0 = c0 - base; m0 = m0 < 0 ? 0 : (m0 > 32 ? 32 : m0);
            int m1 = c1 - base; m1 = m1 < 0 ? 0 : (m1 > 32 ? 32 : m1);
            int mm = m0 > m1 ? m0 : m1;
            int col0 = (lane < m0) ? g_col[s0 + base + lane] : 0;
            int col1 = (lane < m1) ? g_col[s1 + base + lane] : 0;
            for (int t = 0; t < mm; t += 4) {
                int i00 = __shfl_sync(0xffffffffu, col0, t);
                int i01 = __shfl_sync(0xffffffffu, col0, t + 1);
                int i02 = __shfl_sync(0xffffffffu, col0, t + 2);
                int i03 = __shfl_sync(0xffffffffu, col0, t + 3);
                int i10 = __shfl_sync(0xffffffffu, col1, t);
                int i11 = __shfl_sync(0xffffffffu, col1, t + 1);
                int i12 = __shfl_sync(0xffffffffu, col1, t + 2);
                int i13 = __shfl_sync(0xffffffffu, col1, t + 3);
                // 8 independent loads in flight
                float2 u00 = xs[i00 * 32 + lane];
                float2 u01 = xs[i01 * 32 + lane];
                float2 u02 = xs[i02 * 32 + lane];
                float2 u03 = xs[i03 * 32 + lane];
                float2 u10 = xs[i10 * 32 + lane];
                float2 u11 = xs[i11 * 32 + lane];
                float2 u12 = xs[i12 * 32 + lane];
                float2 u13 = xs[i13 * 32 + lane];
                if (t     < m0) { a0 += u00.x; a1 += u00.y; }
                if (t + 1 < m0) { a0 += u01.x; a1 += u01.y; }
                if (t + 2 < m0) { a0 += u02.x; a1 += u02.y; }
                if (t + 3 < m0) { a0 += u03.x; a1 += u03.y; }
                if (t     < m1) { b0 += u10.x; b1 += u10.y; }
                if (t + 1 < m1) { b0 += u11.x; b1 += u11.y; }
                if (t + 2 < m1) { b0 += u12.x; b1 += u12.y; }
                if (t + 3 < m1) { b0 += u13.x; b1 += u13.y; }
            }
        }
        float inv0 = 1.0f / (float)(c0 + 1);
        a_s[nl0 * PAD + 2 * lane]     = a0 * inv0;
        a_s[nl0 * PAD + 2 * lane + 1] = a1 * inv0;
        if (v1) {
            float inv1 = 1.0f / (float)(c1 + 1);
            a_s[(nl0 + 1) * PAD + 2 * lane]     = b0 * inv1;
            a_s[(nl0 + 1) * PAD + 2 * lane + 1] = b1 * inv1;
        }
    }
    __syncthreads();

    // GEMM: 2 nodes x 8 feats per thread
    const int nrow = (tid >> 3) << 1;   // 0,2,...,126
    const int fcol = (tid & 7) << 3;    // 0,8,...,56

    float acc[2][8];
    #pragma unroll
    for (int i = 0; i < 2; i++)
        #pragma unroll
        for (int f = 0; f < 8; f++) acc[i][f] = 0.f;

    #pragma unroll 8
    for (int kk = 0; kk < DIM; kk++) {
        float wlv[8], wrv[8];
        *(float4*)&wlv[0] = *(const float4*)&wl_s[kk * DIM + fcol];
        *(float4*)&wlv[4] = *(const float4*)&wl_s[kk * DIM + fcol + 4];
        *(float4*)&wrv[0] = *(const float4*)&wr_s[kk * DIM + fcol];
        *(float4*)&wrv[4] = *(const float4*)&wr_s[kk * DIM + fcol + 4];
        #pragma unroll
        for (int i = 0; i < 2; i++) {
            float av = a_s[(nrow + i) * PAD + kk];
            float xv = x_s[(nrow + i) * PAD + kk];
            #pragma unroll
            for (int f = 0; f < 8; f++)
                acc[i][f] += av * wlv[f] + xv * wrv[f];
        }
    }

    float bv[8];
    *(float4*)&bv[0] = *(const float4*)(bl + fcol);
    *(float4*)&bv[4] = *(const float4*)(bl + fcol + 4);

    #pragma unroll
    for (int i = 0; i < 2; i++) {
        int node = node0 + nrow + i;
        if (node < N_NODES) {
            float4 o0, o1;
            o0.x = fmaxf(acc[i][0] + bv[0], 0.f);
            o0.y = fmaxf(acc[i][1] + bv[1], 0.f);
            o0.z = fmaxf(acc[i][2] + bv[2], 0.f);
            o0.w = fmaxf(acc[i][3] + bv[3], 0.f);
            o1.x = fmaxf(acc[i][4] + bv[4], 0.f);
            o1.y = fmaxf(acc[i][5] + bv[5], 0.f);
            o1.z = fmaxf(acc[i][6] + bv[6], 0.f);
            o1.w = fmaxf(acc[i][7] + bv[7], 0.f);
            *(float4*)(out + node * DIM + fcol)     = o0;
            *(float4*)(out + node * DIM + fcol + 4) = o1;
        }
    }
}

// ------------------------------------------------------------------ launch
extern "C" void kernel_launch(void* const* d_in, const int* in_sizes, int n_in,
                              void* d_out, int out_size) {
    const float* x   = (const float*)d_in[0];
    const int*   ei  = (const int*)  d_in[1];
    const float* Wl0 = (const float*)d_in[2];
    const float* bl0 = (const float*)d_in[3];
    const float* Wr0 = (const float*)d_in[4];
    const float* Wl1 = (const float*)d_in[5];
    const float* bl1 = (const float*)d_in[6];
    const float* Wr1 = (const float*)d_in[7];
    float* out = (float*)d_out;

    const int LAYER_SMEM = (8192 + 2 * 128 * PAD) * sizeof(float);  // 99328 B
    cudaFuncSetAttribute(k_layer, cudaFuncAttributeMaxDynamicSharedMemorySize,
                         LAYER_SMEM);

    int layer_blocks = (N_NODES + 127) / 128;
    int edge4_blocks = (N_EDGES / 4 + 255) / 256;

    k_hist      <<<edge4_blocks, 256>>>(ei);                                  // 1
    k_scan_chain<<<NCHUNK, 1024>>>();                                         // 2
    k_scatter   <<<edge4_blocks, 256>>>(ei);                                  // 3
    k_layer     <<<layer_blocks, 512, LAYER_SMEM>>>(x,    Wl0, bl0, Wr0, g_x1); // 4 <- ncu
    k_layer     <<<layer_blocks, 512, LAYER_SMEM>>>(g_x1, Wl1, bl1, Wr1, out);  // 5
}

// round 15
// speedup vs baseline: 1.1086x; 1.1086x over previous
#include <cuda_runtime.h>

#define N_NODES 50000
#define N_EDGES 800000
#define DIM 64
#define NCHUNK 49            // ceil(50000/1024)
#define PAD 65               // smem row pitch (floats), conflict-free
#define NPB 96               // nodes per block
#define THR 768              // threads per block (24 warps, 4 nodes/warp)

// Scratch (device globals — no allocation allowed). BSS zero-init at load.
__device__ int   g_deg[N_NODES];
__device__ int   g_row[N_NODES + 1];
__device__ int   g_cur[N_NODES];
__device__ int   g_col[N_EDGES];
__device__ float g_x1[N_NODES * DIM];
__device__ int   g_chain_val[NCHUNK];
__device__ int   g_chain_flag[NCHUNK];   // epoch counts, never reset

// ------------------------------------------------------------------ hist
__global__ void k_hist(const int* __restrict__ ei) {
    int t = blockIdx.x * blockDim.x + threadIdx.x;
    if (t < N_EDGES / 4) {
        int4 d = ((const int4*)(ei + N_EDGES))[t];
        atomicAdd(&g_deg[d.x], 1);
        atomicAdd(&g_deg[d.y], 1);
        atomicAdd(&g_deg[d.z], 1);
        atomicAdd(&g_deg[d.w], 1);
    }
}

// -------------------- chained exclusive scan (one kernel, 49 blocks) -----
__global__ void __launch_bounds__(1024) k_scan_chain() {
    __shared__ int wsum[32];
    __shared__ int s_base;
    int t = threadIdx.x, lane = t & 31, wid = t >> 5;
    int b = blockIdx.x;
    int i = b * 1024 + t;
    int v = 0;
    if (i < N_NODES) { v = g_deg[i]; g_deg[i] = 0; }
    int sc = v;
    #pragma unroll
    for (int off = 1; off < 32; off <<= 1) {
        int n = __shfl_up_sync(0xffffffffu, sc, off);
        if (lane >= off) sc += n;
    }
    if (lane == 31) wsum[wid] = sc;
    __syncthreads();
    if (wid == 0) {
        int w = wsum[lane];
        #pragma unroll
        for (int off = 1; off < 32; off <<= 1) {
            int n = __shfl_up_sync(0xffffffffu, w, off);
            if (lane >= off) w += n;
        }
        wsum[lane] = w;
    }
    __syncthreads();
    int wpre  = (wid > 0) ? wsum[wid - 1] : 0;
    int total = wsum[31];
    if (t == 0) {
        int E = g_chain_flag[b];
        int base = 0;
        if (b > 0) {
            while (atomicAdd(&g_chain_flag[b - 1], 0) <= E) {}
            __threadfence();
            base = g_chain_val[b - 1];
        }
        g_chain_val[b] = base + total;
        __threadfence();
        atomicExch(&g_chain_flag[b], E + 1);
        s_base = base;
    }
    __syncthreads();
    int ex = s_base + wpre + sc - v;
    if (i < N_NODES) { g_row[i] = ex; g_cur[i] = ex; }
    if (i == 0) g_row[N_NODES] = N_EDGES;
}

// --------------------------------------------------------------- scatter
__global__ void k_scatter(const int* __restrict__ ei) {
    int t = blockIdx.x * blockDim.x + threadIdx.x;
    if (t < N_EDGES / 4) {
        int4 s = ((const int4*)ei)[t];
        int4 d = ((const int4*)(ei + N_EDGES))[t];
        g_col[atomicAdd(&g_cur[d.x], 1)] = s.x;
        g_col[atomicAdd(&g_cur[d.y], 1)] = s.y;
        g_col[atomicAdd(&g_cur[d.z], 1)] = s.z;
        g_col[atomicAdd(&g_cur[d.w], 1)] = s.w;
    }
}

// ------------- fused layer: aggregation + GEMM + bias + relu --------------
// Block owns 96 nodes, 768 threads = 24 warps (4 nodes per warp).
// smem 80.8KB -> 2 blocks/SM -> 48 warps/SM (75% occ): doubles the number of
// concurrent independent node-gathers per SM vs the 512-thread version.
__global__ void __launch_bounds__(THR, 2) k_layer(const float* __restrict__ x,
                                                  const float* __restrict__ Wl,
                                                  const float* __restrict__ bl,
                                                  const float* __restrict__ Wr,
                                                  float* __restrict__ out) {
    extern __shared__ float sm[];
    float* wl_s = sm;                     // [64*64]
    float* wr_s = sm + 4096;              // [64*64]
    float* a_s  = sm + 8192;              // [96][PAD]
    float* x_s  = sm + 8192 + NPB * PAD;  // [96][PAD]

    const int tid   = threadIdx.x;
    const int lane  = tid & 31;
    const int w     = tid >> 5;           // warp 0..23
    const int node0 = blockIdx.x * NPB;

    // stage weights (coalesced float4)
    for (int i = tid; i < DIM * DIM / 4; i += THR) {
        ((float4*)wl_s)[i] = ((const float4*)Wl)[i];
        ((float4*)wr_s)[i] = ((const float4*)Wr)[i];
    }
    // stage x rows: 96*16 = 1536 float4, 2 per thread
    for (int i = tid; i < NPB * 16; i += THR) {
        int nl = i >> 4;          // node within block
        int kq = (i & 15) * 4;    // k offset
        int node = node0 + nl;
        if (node < N_NODES) {
            float4 v = *(const float4*)(x + node * DIM + kq);
            x_s[nl * PAD + kq + 0] = v.x;
            x_s[nl * PAD + kq + 1] = v.y;
            x_s[nl * PAD + kq + 2] = v.z;
            x_s[nl * PAD + kq + 3] = v.w;
        }
    }
    __syncthreads();

    // aggregation: warp w -> nodes w*4 .. w*4+3 (mean incl. self)
    const float2* xs = (const float2*)x;
    #pragma unroll 1
    for (int q = 0; q < 4; q++) {
        int nl = w * 4 + q;
        int n  = node0 + nl;
        if (n >= N_NODES) break;
        float a0 = x_s[nl * PAD + 2 * lane];
        float a1 = x_s[nl * PAD + 2 * lane + 1];
        int start = g_row[n];
        int cnt   = g_row[n + 1] - start;
        for (int base = 0; base < cnt; base += 32) {
            int rem = cnt - base;
            int m   = rem < 32 ? rem : 32;
            int c   = (lane < m) ? g_col[start + base + lane] : 0;
            int t = 0;
            for (; t + 4 <= m; t += 4) {
                int s0 = __shfl_sync(0xffffffffu, c, t);
                int s1 = __shfl_sync(0xffffffffu, c, t + 1);
                int s2 = __shfl_sync(0xffffffffu, c, t + 2);
                int s3 = __shfl_sync(0xffffffffu, c, t + 3);
                float2 v0 = xs[s0 * 32 + lane];
                float2 v1 = xs[s1 * 32 + lane];
                float2 v2 = xs[s2 * 32 + lane];
                float2 v3 = xs[s3 * 32 + lane];
                a0 += v0.x; a1 += v0.y;
                a0 += v1.x; a1 += v1.y;
                a0 += v2.x; a1 += v2.y;
                a0 += v3.x; a1 += v3.y;
            }
            for (; t < m; t++) {
                int s = __shfl_sync(0xffffffffu, c, t);
                float2 vv = xs[s * 32 + lane];
                a0 += vv.x; a1 += vv.y;
            }
        }
        float inv = 1.0f / (float)(cnt + 1);
        a_s[nl * PAD + 2 * lane]     = a0 * inv;
        a_s[nl * PAD + 2 * lane + 1] = a1 * inv;
    }
    __syncthreads();

    // GEMM: 2 nodes x 4 feats per thread (48 pairs x 16 fcol-groups = 768)
    const int nrow = (tid >> 4) << 1;   // 0,2,...,94
    const int fc   = (tid & 15) << 2;   // 0,4,...,60

    float acc[2][4];
    #pragma unroll
    for (int i = 0; i < 2; i++)
        #pragma unroll
        for (int f = 0; f < 4; f++) acc[i][f] = 0.f;

    #pragma unroll 8
    for (int kk = 0; kk < DIM; kk++) {
        float4 wlv = *(const float4*)&wl_s[kk * DIM + fc];
        float4 wrv = *(const float4*)&wr_s[kk * DIM + fc];
        #pragma unroll
        for (int i = 0; i < 2; i++) {
            float av = a_s[(nrow + i) * PAD + kk];
            float xv = x_s[(nrow + i) * PAD + kk];
            acc[i][0] += av * wlv.x + xv * wrv.x;
            acc[i][1] += av * wlv.y + xv * wrv.y;
            acc[i][2] += av * wlv.z + xv * wrv.z;
            acc[i][3] += av * wlv.w + xv * wrv.w;
        }
    }

    float4 bv = *(const float4*)(bl + fc);

    #pragma unroll
    for (int i = 0; i < 2; i++) {
        int node = node0 + nrow + i;
        if (node < N_NODES) {
            float4 o;
            o.x = fmaxf(acc[i][0] + bv.x, 0.f);
            o.y = fmaxf(acc[i][1] + bv.y, 0.f);
            o.z = fmaxf(acc[i][2] + bv.z, 0.f);
            o.w = fmaxf(acc[i][3] + bv.w, 0.f);
            *(float4*)(out + node * DIM + fc) = o;
        }
    }
}

// ------------------------------------------------------------------ launch
extern "C" void kernel_launch(void* const* d_in, const int* in_sizes, int n_in,
                              void* d_out, int out_size) {
    const float* x   = (const float*)d_in[0];
    const int*   ei  = (const int*)  d_in[1];
    const float* Wl0 = (const float*)d_in[2];
    const float* bl0 = (const float*)d_in[3];
    const float* Wr0 = (const float*)d_in[4];
    const float* Wl1 = (const float*)d_in[5];
    const float* bl1 = (const float*)d_in[6];
    const float* Wr1 = (const float*)d_in[7];
    float* out = (float*)d_out;

    const int LAYER_SMEM = (8192 + 2 * NPB * PAD) * sizeof(float);  // 82688 B
    cudaFuncSetAttribute(k_layer, cudaFuncAttributeMaxDynamicSharedMemorySize,
                         LAYER_SMEM);

    int layer_blocks = (N_NODES + NPB - 1) / NPB;   // 521
    int edge4_blocks = (N_EDGES / 4 + 255) / 256;

    k_hist      <<<edge4_blocks, 256>>>(ei);                                   // 1
    k_scan_chain<<<NCHUNK, 1024>>>();                                          // 2
    k_scatter   <<<edge4_blocks, 256>>>(ei);                                   // 3
    k_layer     <<<layer_blocks, THR, LAYER_SMEM>>>(x,    Wl0, bl0, Wr0, g_x1); // 4 <- ncu
    k_layer     <<<layer_blocks, THR, LAYER_SMEM>>>(g_x1, Wl1, bl1, Wr1, out);  // 5
}